// round 3
// baseline (speedup 1.0000x reference)
#include <cuda_runtime.h>

// EdgeNetwork, factored + sorted-by-neighbor:
//   T[a][k][i]  = sum_j K[k][i*16+j] * A[a][j]   (per-atom precompute)
//   Tb[a][i]    = sum_j bias[i*16+j] * A[a][j]
//   edges counting-sorted by nb; one warp per atom keeps T[a] in smem
//   msg[e][i]   = sum_k b[e][k] * T[nb][k][i] + Tb[nb][i]
//   out[dst_e] += msg[e]   (red.global.add.v4)

#define MAX_ATOMS 20000
#define MAX_EDGES 640000

__device__ float g_T[MAX_ATOMS * 256];     // [a][k][i], i fastest
__device__ float g_Tb[MAX_ATOMS * 16];     // [a][i]
__device__ int   g_hist[MAX_ATOMS];
__device__ int   g_off[MAX_ATOMS + 1];
__device__ int   g_cursor[MAX_ATOMS];
__device__ int2  g_sorted[MAX_EDGES];      // (e, dst) in nb-sorted order

__device__ __forceinline__ void red_add_v4(float* addr, float4 v) {
    asm volatile("red.global.add.v4.f32 [%0], {%1,%2,%3,%4};"
                 :: "l"(addr), "f"(v.x), "f"(v.y), "f"(v.z), "f"(v.w)
                 : "memory");
}

// ---------------- Phase 1: per-atom precompute (64 atoms / 256-thread block) --
#define APB 64
__global__ void precompute_T(const float* __restrict__ A,
                             const float* __restrict__ Kmat,
                             const float* __restrict__ bias,
                             int n_atoms) {
    __shared__ float Ks[16 * 256];
    __shared__ float Bs[256];
    __shared__ float As[APB * 16];

    const int tid = threadIdx.x;  // 256 threads

    // piggyback: zero the nb-histogram for the sort phase
    {
        int gid = blockIdx.x * 256 + tid;
        if (gid < n_atoms) g_hist[gid] = 0;
    }

    #pragma unroll
    for (int r = 0; r < 16; ++r)
        Ks[r * 256 + tid] = Kmat[r * 256 + tid];
    Bs[tid] = bias[tid];

    const int a0 = blockIdx.x * APB;
    #pragma unroll
    for (int r = 0; r < APB * 16 / 256; ++r) {
        int idx = r * 256 + tid;
        int gidx = a0 * 16 + idx;
        As[idx] = (gidx < n_atoms * 16) ? A[gidx] : 0.f;
    }
    __syncthreads();

    const int k = tid >> 4;
    const int i = tid & 15;

    float kv[16];
    #pragma unroll
    for (int j = 0; j < 16; ++j)
        kv[j] = Ks[k * 256 + i * 16 + j];

    for (int la = 0; la < APB; ++la) {
        int a = a0 + la;
        if (a >= n_atoms) break;
        float s = 0.f;
        #pragma unroll
        for (int j = 0; j < 16; ++j)
            s += kv[j] * As[la * 16 + j];
        g_T[(size_t)a * 256 + tid] = s;  // coalesced: a*256 + k*16 + i
    }

    // Tb: tid -> (i = tid&15, la strided by 16)
    {
        const int ib = tid & 15;
        float bv[16];
        #pragma unroll
        for (int j = 0; j < 16; ++j) bv[j] = Bs[ib * 16 + j];
        for (int la = tid >> 4; la < APB; la += 16) {
            int a = a0 + la;
            if (a >= n_atoms) continue;
            float s = 0.f;
            #pragma unroll
            for (int j = 0; j < 16; ++j)
                s += bv[j] * As[la * 16 + j];
            g_Tb[a * 16 + ib] = s;
        }
    }
}

// ---------------- Phase 2: histogram of nb ----------------------------------
__global__ void hist_kernel(const int* __restrict__ pairs, int n_edges) {
    int e = blockIdx.x * blockDim.x + threadIdx.x;
    if (e < n_edges) {
        int nb = pairs[2 * e + 1];
        atomicAdd(&g_hist[nb], 1);
    }
}

// ---------------- Phase 3: exclusive scan (single block, 1024 threads) ------
__global__ void scan_kernel(int n_atoms) {
    __shared__ int part[1024];
    const int t = threadIdx.x;
    const int chunk = (n_atoms + 1023) / 1024;
    const int st = t * chunk;

    int s = 0;
    for (int i = 0; i < chunk; ++i) {
        int a = st + i;
        if (a < n_atoms) s += g_hist[a];
    }
    part[t] = s;
    __syncthreads();
    for (int off = 1; off < 1024; off <<= 1) {
        int v = (t >= off) ? part[t - off] : 0;
        __syncthreads();
        part[t] += v;
        __syncthreads();
    }
    int run = (t == 0) ? 0 : part[t - 1];
    for (int i = 0; i < chunk; ++i) {
        int a = st + i;
        if (a < n_atoms) {
            g_off[a] = run;
            g_cursor[a] = run;
            run += g_hist[a];
        }
    }
    if (t == 1023) g_off[n_atoms] = part[1023];
}

// ---------------- Phase 4: scatter edges into nb-sorted order ---------------
__global__ void scatter_kernel(const int* __restrict__ pairs, int n_edges) {
    int e = blockIdx.x * blockDim.x + threadIdx.x;
    if (e < n_edges) {
        int2 pr = reinterpret_cast<const int2*>(pairs)[e];
        int pos = atomicAdd(&g_cursor[pr.y], 1);
        g_sorted[pos] = make_int2(e, pr.x);  // (edge id, dst)
    }
}

// ---------------- Phase 5: main edge kernel (one warp per atom) -------------
// Warp holds T[a] (256 f) + Tb[a] (16 f) in its smem slab.
// 8 lanes per edge, 4 edges per warp-iteration:
//   lanes 0..3 accumulate k=2k2, lanes 4..7 k=2k2+1, combine via shfl_xor(4).
#define WPB 8
__global__ void edge_main(const float* __restrict__ bond,
                          float* __restrict__ out,
                          int n_atoms) {
    __shared__ float Ts[WPB][256];
    __shared__ float Tbs[WPB][16];

    const int lane = threadIdx.x & 31;
    const int w = threadIdx.x >> 5;
    const int a = blockIdx.x * WPB + w;
    if (a >= n_atoms) return;

    // load T[a], Tb[a] into this warp's slab
    {
        const float4* Tsrc = reinterpret_cast<const float4*>(g_T + (size_t)a * 256);
        float4* Tdst = reinterpret_cast<float4*>(Ts[w]);
        Tdst[lane] = Tsrc[lane];
        Tdst[lane + 32] = Tsrc[lane + 32];
        if (lane < 4)
            reinterpret_cast<float4*>(Tbs[w])[lane] =
                reinterpret_cast<const float4*>(g_Tb + a * 16)[lane];
    }
    __syncwarp();

    const int start = g_off[a];
    const int cnt = g_off[a + 1] - start;
    if (cnt == 0) return;

    const int t = lane & 7;   // position within edge-group
    const int g = lane >> 3;  // which of 4 edges this iteration

    const float4* Tv = reinterpret_cast<const float4*>(Ts[w]);
    const float4* Tbv = reinterpret_cast<const float4*>(Tbs[w]);

    for (int base = 0; base < cnt; base += 4) {
        const int slot = base + g;
        const bool v = (slot < cnt);
        const int sidx = start + (v ? slot : cnt - 1);
        const int2 ed = g_sorted[sidx];           // (e, dst), broadcast in group

        // bond[e][2t], bond[e][2t+1]: 64B coalesced per 8-lane group
        const float2 bv = reinterpret_cast<const float2*>(bond)[ed.x * 8 + t];

        float4 acc = (t < 4) ? Tbv[t] : make_float4(0.f, 0.f, 0.f, 0.f);

        #pragma unroll
        for (int k2 = 0; k2 < 8; ++k2) {
            const float b_lo = __shfl_sync(0xffffffffu, bv.x, k2, 8);
            const float b_hi = __shfl_sync(0xffffffffu, bv.y, k2, 8);
            const float bk = (t < 4) ? b_lo : b_hi;
            const float4 tv = Tv[k2 * 8 + t];     // smem, broadcast across groups
            acc.x += bk * tv.x;
            acc.y += bk * tv.y;
            acc.z += bk * tv.z;
            acc.w += bk * tv.w;
        }

        acc.x += __shfl_xor_sync(0xffffffffu, acc.x, 4);
        acc.y += __shfl_xor_sync(0xffffffffu, acc.y, 4);
        acc.z += __shfl_xor_sync(0xffffffffu, acc.z, 4);
        acc.w += __shfl_xor_sync(0xffffffffu, acc.w, 4);

        if (v && t < 4)
            red_add_v4(out + ed.y * 16 + 4 * t, acc);
    }
}

extern "C" void kernel_launch(void* const* d_in, const int* in_sizes, int n_in,
                              void* d_out, int out_size) {
    const float* A     = (const float*)d_in[0];
    const float* bond  = (const float*)d_in[1];
    const int*   pairs = (const int*)  d_in[2];
    const float* Kmat  = (const float*)d_in[3];
    const float* bias  = (const float*)d_in[4];
    float* out = (float*)d_out;

    const int n_atoms = in_sizes[0] / 16;
    const int n_edges = in_sizes[2] / 2;

    cudaMemsetAsync(out, 0, (size_t)out_size * sizeof(float), 0);

    precompute_T<<<(n_atoms + APB - 1) / APB, 256>>>(A, Kmat, bias, n_atoms);
    hist_kernel<<<(n_edges + 255) / 256, 256>>>(pairs, n_edges);
    scan_kernel<<<1, 1024>>>(n_atoms);
    scatter_kernel<<<(n_edges + 255) / 256, 256>>>(pairs, n_edges);
    edge_main<<<(n_atoms + WPB - 1) / WPB, WPB * 32>>>(bond, out, n_atoms);
}

// round 4
// speedup vs baseline: 2.1049x; 2.1049x over previous
#include <cuda_runtime.h>
#include <cuda_fp16.h>

// EdgeNetwork factored (fp16 T table):
//   T[a][k][i]  = sum_j K[k][i*16+j] * A[a][j]   (per-atom, stored __half)
//   Tb[a][i]    = sum_j bias[i*16+j] * A[a][j]   (fp32)
//   msg[e][i]   = sum_k b[e][k] * T[nb_e][k][i] + Tb[nb_e][i]   (fp32 accum)
//   out[dst_e] += msg[e]   (red.global.add.v4.f32)

#define MAX_ATOMS 20000

__device__ __half g_Th[MAX_ATOMS * 256];   // [a][k][i], i fastest, 512B/atom
__device__ float  g_Tb[MAX_ATOMS * 16];    // [a][i]

__device__ __forceinline__ void red_add_v4(float* addr, float4 v) {
    asm volatile("red.global.add.v4.f32 [%0], {%1,%2,%3,%4};"
                 :: "l"(addr), "f"(v.x), "f"(v.y), "f"(v.z), "f"(v.w)
                 : "memory");
}

// ---------------- Phase 1: per-atom precompute (64 atoms / 256-thread block) -
#define APB 64
__global__ void precompute_T(const float* __restrict__ A,
                             const float* __restrict__ Kmat,
                             const float* __restrict__ bias,
                             int n_atoms) {
    __shared__ float Ks[16 * 256];
    __shared__ float Bs[256];
    __shared__ float As[APB * 16];

    const int tid = threadIdx.x;  // 256 threads

    #pragma unroll
    for (int r = 0; r < 16; ++r)
        Ks[r * 256 + tid] = Kmat[r * 256 + tid];
    Bs[tid] = bias[tid];

    const int a0 = blockIdx.x * APB;
    #pragma unroll
    for (int r = 0; r < APB * 16 / 256; ++r) {
        int idx = r * 256 + tid;
        int gidx = a0 * 16 + idx;
        As[idx] = (gidx < n_atoms * 16) ? A[gidx] : 0.f;
    }
    __syncthreads();

    const int k = tid >> 4;
    const int i = tid & 15;

    float kv[16];
    #pragma unroll
    for (int j = 0; j < 16; ++j)
        kv[j] = Ks[k * 256 + i * 16 + j];

    for (int la = 0; la < APB; ++la) {
        int a = a0 + la;
        if (a >= n_atoms) break;
        float s = 0.f;
        #pragma unroll
        for (int j = 0; j < 16; ++j)
            s += kv[j] * As[la * 16 + j];
        g_Th[(size_t)a * 256 + tid] = __float2half_rn(s);  // coalesced
    }

    // Tb: thread -> (i = tid&15, la strided by 16)
    {
        const int ib = tid & 15;
        float bv[16];
        #pragma unroll
        for (int j = 0; j < 16; ++j) bv[j] = Bs[ib * 16 + j];
        for (int la = tid >> 4; la < APB; la += 16) {
            int a = a0 + la;
            if (a >= n_atoms) continue;
            float s = 0.f;
            #pragma unroll
            for (int j = 0; j < 16; ++j)
                s += bv[j] * As[la * 16 + j];
            g_Tb[a * 16 + ib] = s;
        }
    }
}

// ---------------- Phase 2: edge kernel, 8 threads/edge, fp16 T --------------
// Lane t (in 8-group): ih = t&1 selects i-half (8 i's), kc = t>>1 the k-class.
// Iteration q in [0,4): lane loads T[nb][4q+kc][ih*8 .. ih*8+7] as one uint4
// (16B); the 8-lane group covers exactly 128B contiguous -> 1 wavefront/iter.
// Coefficient b[e][4q+kc] comes via ONE shfl per iteration (register picked at
// compile time because q is unrolled). Reduction over kc: shfl_xor 2 then 4.
__global__ void edge_msgs(const float* __restrict__ bond,
                          const int* __restrict__ pairs,
                          float* __restrict__ out,
                          int n_edges) {
    const int gid = blockIdx.x * blockDim.x + threadIdx.x;
    const int e = gid >> 3;
    const int t = gid & 7;
    const bool valid = (e < n_edges);
    const int ec = valid ? e : (n_edges - 1);  // keep lanes active for shfl

    const int2 pr = reinterpret_cast<const int2*>(pairs)[ec];

    // bond coefficients: b0 = b[e][t], b1 = b[e][t+8]
    const float b0 = bond[ec * 16 + t];
    const float b1 = bond[ec * 16 + 8 + t];

    const __half* Trow = g_Th + (size_t)pr.y * 256;

    float acc[8] = {0.f, 0.f, 0.f, 0.f, 0.f, 0.f, 0.f, 0.f};

    #pragma unroll
    for (int q = 0; q < 4; ++q) {
        // k = 4q + (t>>1); its b lives in reg (k<8 ? b0 : b1) of lane (k & 7)
        const int src = (q & 1) * 4 + (t >> 1);
        const float bk = __shfl_sync(0xffffffffu, (q < 2) ? b0 : b1, src, 8);

        const uint4 tv = *reinterpret_cast<const uint4*>(Trow + q * 64 + t * 8);
        const __half2* h = reinterpret_cast<const __half2*>(&tv);
        #pragma unroll
        for (int p = 0; p < 4; ++p) {
            const float2 f = __half22float2(h[p]);
            acc[2 * p]     += bk * f.x;
            acc[2 * p + 1] += bk * f.y;
        }
    }

    // reduce over the 4 k-classes (lanes differing in bits 1,2; same ih = t&1)
    #pragma unroll
    for (int p = 0; p < 8; ++p) {
        acc[p] += __shfl_xor_sync(0xffffffffu, acc[p], 2, 8);
        acc[p] += __shfl_xor_sync(0xffffffffu, acc[p], 4, 8);
    }

    // lanes 0..3 emit: i-quad = (t&1)*8 + (t>>1)*4
    if (valid && t < 4) {
        const int qidx = (t & 1) * 2 + (t >> 1);
        const float4 tb =
            reinterpret_cast<const float4*>(g_Tb + pr.y * 16)[qidx];
        float4 v;
        if (t < 2) v = make_float4(acc[0], acc[1], acc[2], acc[3]);
        else       v = make_float4(acc[4], acc[5], acc[6], acc[7]);
        v.x += tb.x; v.y += tb.y; v.z += tb.z; v.w += tb.w;
        red_add_v4(out + pr.x * 16 + qidx * 4, v);
    }
}

extern "C" void kernel_launch(void* const* d_in, const int* in_sizes, int n_in,
                              void* d_out, int out_size) {
    const float* A     = (const float*)d_in[0];  // atom_features [n_atoms,16]
    const float* bond  = (const float*)d_in[1];  // bond_features [n_edges,16]
    const int*   pairs = (const int*)  d_in[2];  // pair_indices  [n_edges,2]
    const float* Kmat  = (const float*)d_in[3];  // kernel [16,256]
    const float* bias  = (const float*)d_in[4];  // bias [256]
    float* out = (float*)d_out;                  // [n_atoms,16]

    const int n_atoms = in_sizes[0] / 16;
    const int n_edges = in_sizes[2] / 2;

    cudaMemsetAsync(out, 0, (size_t)out_size * sizeof(float), 0);

    precompute_T<<<(n_atoms + APB - 1) / APB, 256>>>(A, Kmat, bias, n_atoms);

    {
        long long total_threads = (long long)n_edges * 8;
        int blocks = (int)((total_threads + 255) / 256);
        edge_msgs<<<blocks, 256>>>(bond, pairs, out, n_edges);
    }
}

// round 5
// speedup vs baseline: 2.3418x; 1.1125x over previous
#include <cuda_runtime.h>
#include <cuda_fp16.h>

// EdgeNetwork factored (fp16 T table, half2 edge math):
//   T[a][k][i]  = sum_j K[k][i*16+j] * A[a][j]   (per-atom, stored __half)
//   Tb[a][i]    = sum_j bias[i*16+j] * A[a][j]   (fp32)
//   msg[e][i]   = sum_k b[e][k] * T[nb_e][k][i] + Tb[nb_e][i]
//   out[dst_e] += msg[e]   (red.global.add.v4.f32)

#define MAX_ATOMS 20000

__device__ __half g_Th[MAX_ATOMS * 256];   // [a][k][i], i fastest, 512B/atom
__device__ float  g_Tb[MAX_ATOMS * 16];    // [a][i]

__device__ __forceinline__ void red_add_v4(float* addr, float4 v) {
    asm volatile("red.global.add.v4.f32 [%0], {%1,%2,%3,%4};"
                 :: "l"(addr), "f"(v.x), "f"(v.y), "f"(v.z), "f"(v.w)
                 : "memory");
}

// ---------------- Phase 1: per-atom precompute (64 atoms / 256-thread block) -
// As kept as float4 so per-atom smem reads are 4 wide broadcasts, not 16 scalar.
#define APB 64
__global__ void precompute_T(const float* __restrict__ A,
                             const float* __restrict__ Kmat,
                             const float* __restrict__ bias,
                             int n_atoms) {
    __shared__ float  Ks[16 * 256];
    __shared__ float  Bs[256];
    __shared__ float4 As4[APB * 4];   // A rows, 4 float4 per atom

    const int tid = threadIdx.x;  // 256 threads

    #pragma unroll
    for (int r = 0; r < 16; ++r)
        Ks[r * 256 + tid] = Kmat[r * 256 + tid];
    Bs[tid] = bias[tid];

    const int a0 = blockIdx.x * APB;
    {
        // APB*16 floats = APB*4 float4 = 256 float4: one per thread
        int gidx4 = a0 * 4 + tid;            // float4 index into A
        if (gidx4 * 4 < n_atoms * 16)
            As4[tid] = reinterpret_cast<const float4*>(A)[gidx4];
        else
            As4[tid] = make_float4(0.f, 0.f, 0.f, 0.f);
    }
    __syncthreads();

    const int k = tid >> 4;
    const int i = tid & 15;

    float kv[16];
    #pragma unroll
    for (int j = 0; j < 16; ++j)
        kv[j] = Ks[k * 256 + i * 16 + j];

    for (int la = 0; la < APB; ++la) {
        int a = a0 + la;
        if (a >= n_atoms) break;
        float s = 0.f;
        #pragma unroll
        for (int c = 0; c < 4; ++c) {
            const float4 av = As4[la * 4 + c];   // 16B broadcast, 1 wavefront
            s += kv[4 * c + 0] * av.x;
            s += kv[4 * c + 1] * av.y;
            s += kv[4 * c + 2] * av.z;
            s += kv[4 * c + 3] * av.w;
        }
        g_Th[(size_t)a * 256 + tid] = __float2half_rn(s);  // coalesced
    }

    // Tb: thread -> (i = tid&15, la strided by 16)
    {
        const int ib = tid & 15;
        float bv[16];
        #pragma unroll
        for (int j = 0; j < 16; ++j) bv[j] = Bs[ib * 16 + j];
        for (int la = tid >> 4; la < APB; la += 16) {
            int a = a0 + la;
            if (a >= n_atoms) continue;
            float s = 0.f;
            #pragma unroll
            for (int c = 0; c < 4; ++c) {
                const float4 av = As4[la * 4 + c];
                s += bv[4 * c + 0] * av.x;
                s += bv[4 * c + 1] * av.y;
                s += bv[4 * c + 2] * av.z;
                s += bv[4 * c + 3] * av.w;
            }
            g_Tb[a * 16 + ib] = s;
        }
    }
}

// ---------------- Phase 2: edge kernel, 8 threads/edge, all-half2 math ------
// Lane t (in 8-group): ih = t&1 selects i-half (8 i's), kc = t>>1 the k-class.
// Iter q in [0,4): lane loads T[nb][4q+kc][ih*8..ih*8+7] as one uint4 (16B);
// the 8-lane group covers 128B contiguous -> 1 wavefront/iter.
// Accumulate with HFMA2 (4 half2 regs), reduce over kc with 2 shfl_xor+HADD2
// stages, convert to fp32 only at the very end.
__global__ void edge_msgs(const float* __restrict__ bond,
                          const int* __restrict__ pairs,
                          float* __restrict__ out,
                          int n_edges) {
    const int gid = blockIdx.x * blockDim.x + threadIdx.x;
    const int e = gid >> 3;
    const int t = gid & 7;
    const bool valid = (e < n_edges);
    const int ec = valid ? e : (n_edges - 1);  // keep lanes active for shfl

    const int2 pr = reinterpret_cast<const int2*>(pairs)[ec];

    // bond coefficients: b0 = b[e][t], b1 = b[e][t+8]
    const float b0 = bond[ec * 16 + t];
    const float b1 = bond[ec * 16 + 8 + t];

    const __half* Trow = g_Th + (size_t)pr.y * 256;

    __half2 acc[4];
    acc[0] = acc[1] = acc[2] = acc[3] = __half2half2(__float2half(0.f));

    #pragma unroll
    for (int q = 0; q < 4; ++q) {
        // k = 4q + (t>>1); its b lives in reg (q<2 ? b0 : b1) of lane src
        const int src = (q & 1) * 4 + (t >> 1);
        const float bkf = __shfl_sync(0xffffffffu, (q < 2) ? b0 : b1, src, 8);
        const __half2 bk2 = __float2half2_rn(bkf);

        const uint4 tv = *reinterpret_cast<const uint4*>(Trow + q * 64 + t * 8);
        const __half2* h = reinterpret_cast<const __half2*>(&tv);
        #pragma unroll
        for (int p = 0; p < 4; ++p)
            acc[p] = __hfma2(h[p], bk2, acc[p]);
    }

    // reduce over the 4 k-classes (lanes differing in bits 1,2; same ih = t&1)
    #pragma unroll
    for (int p = 0; p < 4; ++p) {
        unsigned u = *reinterpret_cast<unsigned*>(&acc[p]);
        unsigned o = __shfl_xor_sync(0xffffffffu, u, 2, 8);
        acc[p] = __hadd2(acc[p], *reinterpret_cast<__half2*>(&o));
        u = *reinterpret_cast<unsigned*>(&acc[p]);
        o = __shfl_xor_sync(0xffffffffu, u, 4, 8);
        acc[p] = __hadd2(acc[p], *reinterpret_cast<__half2*>(&o));
    }

    // lanes 0..3 emit. lane t: ih = t&1, quad-within-half = t>>1.
    // i-quad index qidx = (t&1)*2 + (t>>1); uses acc[0..1] if t<2 else acc[2..3].
    if (valid && t < 4) {
        const int qidx = (t & 1) * 2 + (t >> 1);
        const float4 tb =
            reinterpret_cast<const float4*>(g_Tb + pr.y * 16)[qidx];
        const float2 f0 = __half22float2(acc[(t < 2) ? 0 : 2]);
        const float2 f1 = __half22float2(acc[(t < 2) ? 1 : 3]);
        float4 v = make_float4(f0.x + tb.x, f0.y + tb.y,
                               f1.x + tb.z, f1.y + tb.w);
        red_add_v4(out + pr.x * 16 + qidx * 4, v);
    }
}

extern "C" void kernel_launch(void* const* d_in, const int* in_sizes, int n_in,
                              void* d_out, int out_size) {
    const float* A     = (const float*)d_in[0];  // atom_features [n_atoms,16]
    const float* bond  = (const float*)d_in[1];  // bond_features [n_edges,16]
    const int*   pairs = (const int*)  d_in[2];  // pair_indices  [n_edges,2]
    const float* Kmat  = (const float*)d_in[3];  // kernel [16,256]
    const float* bias  = (const float*)d_in[4];  // bias [256]
    float* out = (float*)d_out;                  // [n_atoms,16]

    const int n_atoms = in_sizes[0] / 16;
    const int n_edges = in_sizes[2] / 2;

    cudaMemsetAsync(out, 0, (size_t)out_size * sizeof(float), 0);

    precompute_T<<<(n_atoms + APB - 1) / APB, 256>>>(A, Kmat, bias, n_atoms);

    {
        long long total_threads = (long long)n_edges * 8;
        int blocks = (int)((total_threads + 255) / 256);
        edge_msgs<<<blocks, 256>>>(bond, pairs, out, n_edges);
    }
}

// round 6
// speedup vs baseline: 2.5576x; 1.0922x over previous
#include <cuda_runtime.h>
#include <cuda_fp16.h>

// EdgeNetwork factored (fp16 T table, half2 edge math):
//   T[a][k][i]  = sum_j K[k][i*16+j] * A[a][j]   (per-atom, stored __half)
//   Tb[a][i]    = sum_j bias[i*16+j] * A[a][j]   (fp32)
//   msg[e][i]   = sum_k b[e][k] * T[nb_e][k][i] + Tb[nb_e][i]
//   out[dst_e] += msg[e]   (red.global.add.v4.f32)

#define MAX_ATOMS 20000

__device__ __half g_Th[MAX_ATOMS * 256];   // [a][k][i], i fastest, 512B/atom
__device__ float  g_Tb[MAX_ATOMS * 16];    // [a][i]

__device__ __forceinline__ void red_add_v4(float* addr, float4 v) {
    asm volatile("red.global.add.v4.f32 [%0], {%1,%2,%3,%4};"
                 :: "l"(addr), "f"(v.x), "f"(v.y), "f"(v.z), "f"(v.w)
                 : "memory");
}

// ---------------- Phase 1: per-atom precompute -------------------------------
// 16 atoms / 256-thread block (1250 CTAs -> full chip). thread=(k=tid>>4,i=tid&15).
// K stored in smem as [k][i][j] with i-stride 17 -> conflict-free LDS.
// Also zeroes the output (grid x 256 threads == n_atoms*16 floats).
#define APB 16
__global__ void precompute_T(const float* __restrict__ A,
                             const float* __restrict__ Kmat,
                             const float* __restrict__ bias,
                             float* __restrict__ out,
                             int n_atoms) {
    __shared__ float  Ks[16 * 272];   // [k][i*17 + j]
    __shared__ float  Bs[272];        // [i*17 + j]
    __shared__ float4 As4[APB * 4];   // A rows, 4 float4 per atom

    const int tid = threadIdx.x;  // 256 threads
    const int k = tid >> 4;
    const int i = tid & 15;

    // zero this block's slice of out (replaces the memset launch)
    {
        int o = blockIdx.x * 256 + tid;
        if (o < n_atoms * 16) out[o] = 0.f;
    }

    #pragma unroll
    for (int r = 0; r < 16; ++r) {
        float v = Kmat[r * 256 + tid];          // coalesced
        Ks[r * 272 + (tid >> 4) * 17 + (tid & 15)] = v;   // conflict-free
    }
    Bs[(tid >> 4) * 17 + (tid & 15)] = bias[tid];

    const int a0 = blockIdx.x * APB;
    if (tid < APB * 4) {
        int gidx4 = a0 * 4 + tid;               // float4 index into A
        As4[tid] = (gidx4 * 4 < n_atoms * 16)
                 ? reinterpret_cast<const float4*>(A)[gidx4]
                 : make_float4(0.f, 0.f, 0.f, 0.f);
    }
    __syncthreads();

    float kv[16];
    #pragma unroll
    for (int j = 0; j < 16; ++j)
        kv[j] = Ks[k * 272 + i * 17 + j];       // conflict-free

    #pragma unroll
    for (int la = 0; la < APB; ++la) {
        int a = a0 + la;
        if (a >= n_atoms) break;
        float s = 0.f;
        #pragma unroll
        for (int c = 0; c < 4; ++c) {
            const float4 av = As4[la * 4 + c];  // 16B broadcast
            s += kv[4 * c + 0] * av.x;
            s += kv[4 * c + 1] * av.y;
            s += kv[4 * c + 2] * av.z;
            s += kv[4 * c + 3] * av.w;
        }
        g_Th[(size_t)a * 256 + tid] = __float2half_rn(s);  // coalesced
    }

    // Tb: exactly one value per thread (la = tid>>4, ib = tid&15)
    {
        const int la = tid >> 4;
        const int ib = tid & 15;
        const int a = a0 + la;
        if (a < n_atoms) {
            float s = 0.f;
            #pragma unroll
            for (int c = 0; c < 4; ++c) {
                const float4 av = As4[la * 4 + c];
                s += Bs[ib * 17 + 4 * c + 0] * av.x;
                s += Bs[ib * 17 + 4 * c + 1] * av.y;
                s += Bs[ib * 17 + 4 * c + 2] * av.z;
                s += Bs[ib * 17 + 4 * c + 3] * av.w;
            }
            g_Tb[a * 16 + ib] = s;              // coalesced
        }
    }
}

// ---------------- Phase 2: edge kernel, 8 threads/edge, all-half2 math ------
// Lane t (in 8-group): ih = t&1 selects i-half (8 i's), kc = t>>1 the k-class.
// Iter q in [0,4): lane loads T[nb][4q+kc][ih*8..ih*8+7] as one uint4 (16B);
// the 8-lane group covers 128B contiguous -> 1 wavefront/iter.
// Coefficients pre-packed as half2 and shuffled as raw words (1 shfl/iter).
// GUARD=false when n_edges % 32 == 0 (grid covers edges exactly).
template<bool GUARD>
__global__ void edge_msgs(const float* __restrict__ bond,
                          const int* __restrict__ pairs,
                          float* __restrict__ out,
                          int n_edges) {
    const int gid = blockIdx.x * blockDim.x + threadIdx.x;
    int e = gid >> 3;
    const int t = gid & 7;
    bool valid = true;
    if (GUARD) {
        valid = (e < n_edges);
        if (!valid) e = n_edges - 1;   // keep lanes active for shfl
    }

    const int2 pr = reinterpret_cast<const int2*>(pairs)[e];

    // bond coefficients: b[e][t] and b[e][t+8], packed to duplicated half2
    const float b0 = bond[e * 16 + t];
    const float b1 = bond[e * 16 + 8 + t];
    __half2 hb0 = __float2half2_rn(b0);
    __half2 hb1 = __float2half2_rn(b1);
    const unsigned u0 = *reinterpret_cast<unsigned*>(&hb0);
    const unsigned u1 = *reinterpret_cast<unsigned*>(&hb1);

    const __half* Trow = g_Th + (size_t)pr.y * 256;

    __half2 acc[4];
    acc[0] = acc[1] = acc[2] = acc[3] = __float2half2_rn(0.f);

    #pragma unroll
    for (int q = 0; q < 4; ++q) {
        // k = 4q + (t>>1); its coeff lives in word (q<2 ? u0 : u1) of lane src
        const int src = (q & 1) * 4 + (t >> 1);
        unsigned bu = __shfl_sync(0xffffffffu, (q < 2) ? u0 : u1, src, 8);
        const __half2 bk2 = *reinterpret_cast<__half2*>(&bu);

        const uint4 tv = *reinterpret_cast<const uint4*>(Trow + q * 64 + t * 8);
        const __half2* h = reinterpret_cast<const __half2*>(&tv);
        #pragma unroll
        for (int p = 0; p < 4; ++p)
            acc[p] = __hfma2(h[p], bk2, acc[p]);
    }

    // reduce over the 4 k-classes (lanes differing in bits 1,2; same ih = t&1)
    #pragma unroll
    for (int p = 0; p < 4; ++p) {
        unsigned u = *reinterpret_cast<unsigned*>(&acc[p]);
        unsigned o = __shfl_xor_sync(0xffffffffu, u, 2, 8);
        acc[p] = __hadd2(acc[p], *reinterpret_cast<__half2*>(&o));
        u = *reinterpret_cast<unsigned*>(&acc[p]);
        o = __shfl_xor_sync(0xffffffffu, u, 4, 8);
        acc[p] = __hadd2(acc[p], *reinterpret_cast<__half2*>(&o));
    }

    // lanes 0..3 emit. i-quad qidx = (t&1)*2 + (t>>1).
    if ((!GUARD || valid) && t < 4) {
        const int qidx = (t & 1) * 2 + (t >> 1);
        const float4 tb =
            reinterpret_cast<const float4*>(g_Tb + pr.y * 16)[qidx];
        const float2 f0 = __half22float2(acc[(t < 2) ? 0 : 2]);
        const float2 f1 = __half22float2(acc[(t < 2) ? 1 : 3]);
        float4 v = make_float4(f0.x + tb.x, f0.y + tb.y,
                               f1.x + tb.z, f1.y + tb.w);
        red_add_v4(out + pr.x * 16 + qidx * 4, v);
    }
}

extern "C" void kernel_launch(void* const* d_in, const int* in_sizes, int n_in,
                              void* d_out, int out_size) {
    const float* A     = (const float*)d_in[0];  // atom_features [n_atoms,16]
    const float* bond  = (const float*)d_in[1];  // bond_features [n_edges,16]
    const int*   pairs = (const int*)  d_in[2];  // pair_indices  [n_edges,2]
    const float* Kmat  = (const float*)d_in[3];  // kernel [16,256]
    const float* bias  = (const float*)d_in[4];  // bias [256]
    float* out = (float*)d_out;                  // [n_atoms,16]

    const int n_atoms = in_sizes[0] / 16;
    const int n_edges = in_sizes[2] / 2;

    // Phase 1 also zeroes out[] (grid*256 threads cover n_atoms*16 floats)
    precompute_T<<<(n_atoms + APB - 1) / APB, 256>>>(A, Kmat, bias, out, n_atoms);

    if (n_edges % 32 == 0) {
        int blocks = (n_edges * 8) / 256;
        edge_msgs<false><<<blocks, 256>>>(bond, pairs, out, n_edges);
    } else {
        long long total_threads = (long long)n_edges * 8;
        int blocks = (int)((total_threads + 255) / 256);
        edge_msgs<true><<<blocks, 256>>>(bond, pairs, out, n_edges);
    }
}